// round 5
// baseline (speedup 1.0000x reference)
#include <cuda_runtime.h>
#include <cuda_bf16.h>
#include <cstdint>

// ======================= problem constants =======================
#define MDIM 8192
#define KDIM 4096
#define NDIM 4096

// ======================= GEMM tiling =======================
constexpr int BM = 128;            // CTA M tile
constexpr int BN = 256;            // CTA N tile
constexpr int BK = 128;            // K bytes (int8) per stage -> 128B rows
constexpr int STAGES = 4;
constexpr int KITERS = KDIM / BK;  // 32
constexpr int A_BYTES = BM * BK;   // 16 KB
constexpr int B_BYTES = BN * BK;   // 32 KB
constexpr int STAGE_BYTES = A_BYTES + B_BYTES;   // 48 KB
constexpr int SMEM_TOTAL = STAGES * STAGE_BYTES; // 192 KB

// ======================= device scratch (no allocs allowed) =======================
__device__ __align__(1024) int8_t g_xq[(size_t)MDIM * KDIM]; // 32 MB quantized x
__device__ __align__(1024) int8_t g_wq[(size_t)NDIM * KDIM]; // 16 MB packed weights
__device__ unsigned int g_maxbits;
__device__ int g_swapsb;

// ======================= helpers =======================
__device__ __forceinline__ uint32_t smem_u32(const void* p) {
    uint32_t a;
    asm("{ .reg .u64 t; cvta.to.shared.u64 t, %1; cvt.u32.u64 %0, t; }"
        : "=r"(a) : "l"(p));
    return a;
}

__device__ __forceinline__ void cp16(uint32_t dst, const void* src) {
    asm volatile("cp.async.cg.shared.global [%0], [%1], 16;" :: "r"(dst), "l"(src));
}

__device__ __forceinline__ uint32_t lds32(uint32_t addr) {
    uint32_t v;
    asm volatile("ld.shared.b32 %0, [%1];" : "=r"(v) : "r"(addr));
    return v;
}

__device__ __forceinline__ void mma_s8(int* c, const uint32_t* a, uint32_t b0,
                                       uint32_t b1) {
    asm volatile(
        "mma.sync.aligned.m16n8k32.row.col.s32.s8.s8.s32 "
        "{%0,%1,%2,%3}, {%4,%5,%6,%7}, {%8,%9}, {%0,%1,%2,%3};"
        : "+r"(c[0]), "+r"(c[1]), "+r"(c[2]), "+r"(c[3])
        : "r"(a[0]), "r"(a[1]), "r"(a[2]), "r"(a[3]), "r"(b0), "r"(b1));
}

// ======================= preprocessing =======================
__global__ void k_init() { g_maxbits = 0u; }

__global__ void k_maxabs(const float4* __restrict__ x, int n4) {
    unsigned int m = 0;
    for (int i = blockIdx.x * blockDim.x + threadIdx.x; i < n4;
         i += gridDim.x * blockDim.x) {
        float4 v = x[i];
        m = max(m, __float_as_uint(fabsf(v.x)));
        m = max(m, __float_as_uint(fabsf(v.y)));
        m = max(m, __float_as_uint(fabsf(v.z)));
        m = max(m, __float_as_uint(fabsf(v.w)));
    }
    #pragma unroll
    for (int o = 16; o > 0; o >>= 1)
        m = max(m, __shfl_xor_sync(0xffffffffu, m, o));
    if ((threadIdx.x & 31) == 0) atomicMax(&g_maxbits, m);
}

// s_w is strictly positive by construction; bias has negatives. If the
// candidate s_w pointer shows a negative in its first 256 values, swap.
__global__ void k_detect(const float* __restrict__ cand_sw) {
    bool neg = false;
    for (int i = threadIdx.x; i < 256; i += 32) neg |= (cand_sw[i] < 0.0f);
    unsigned b = __ballot_sync(0xffffffffu, neg);
    if (threadIdx.x == 0) g_swapsb = (b != 0u);
}

// x -> int8, matching jnp exactly: round-half-even(x / s_x) clamped to [-127,127].
__global__ void k_quant(const float4* __restrict__ x) {
    int i = blockIdx.x * blockDim.x + threadIdx.x;
    float sx = __fdiv_rn(__uint_as_float(g_maxbits), 127.0f);
    float4 v = x[i];
    int q0 = (int)fminf(fmaxf(rintf(__fdiv_rn(v.x, sx)), -127.f), 127.f);
    int q1 = (int)fminf(fmaxf(rintf(__fdiv_rn(v.y, sx)), -127.f), 127.f);
    int q2 = (int)fminf(fmaxf(rintf(__fdiv_rn(v.z, sx)), -127.f), 127.f);
    int q3 = (int)fminf(fmaxf(rintf(__fdiv_rn(v.w, sx)), -127.f), 127.f);
    unsigned int u = (q0 & 0xFF) | ((q1 & 0xFF) << 8) | ((q2 & 0xFF) << 16) |
                     ((unsigned)(q3 & 0xFF) << 24);
    reinterpret_cast<unsigned int*>(g_xq)[i] = u;
}

// w_q arrives as int32 words (harness has no int8 dtype). Pack low bytes.
__global__ void k_wpack(const int4* __restrict__ w) {
    int i = blockIdx.x * blockDim.x + threadIdx.x;  // one int4 = 4 weights
    int4 p = w[i];
    unsigned int u = (p.x & 0xFF) | ((p.y & 0xFF) << 8) | ((p.z & 0xFF) << 16) |
                     ((unsigned)(p.w & 0xFF) << 24);
    reinterpret_cast<unsigned int*>(g_wq)[i] = u;
}

// ======================= GEMM (int8 IMMA, direct-LDS fragments) =======================
__global__ void __launch_bounds__(256, 1)
k_gemm(const float* __restrict__ p_sw, const float* __restrict__ p_bias,
       float* __restrict__ C) {
    extern __shared__ char smem[];
    const uint32_t sb = smem_u32(smem);
    const int tid = threadIdx.x;
    const int lane = tid & 31;
    const int wid = tid >> 5;
    const int g = lane >> 2;       // fragment row group 0..7
    const int tg = lane & 3;       // thread-in-group 0..3
    const int wm = (wid >> 2) * 64;  // warp M offset (2 warps along M)
    const int wn = (wid & 3) * 64;   // warp N offset (4 warps along N)

    const int m0 = blockIdx.y * BM;
    const int n0 = blockIdx.x * BN;

    // ---- async fill of one stage (16B chunks, XOR-swizzled within 128B rows) ----
    const int a_row = tid >> 1;           // 0..127
    const int a_c0 = (tid & 1) * 4;       // 0 or 4
    const int8_t* Ag = g_xq + (size_t)(m0 + a_row) * KDIM;
    const int8_t* Bg = g_wq + (size_t)(n0 + tid) * KDIM;

    auto fill = [&](int stage, int j) {
        const uint32_t sA = sb + stage * STAGE_BYTES;
        const uint32_t sB = sA + A_BYTES;
        const int kb = j * BK;
        #pragma unroll
        for (int i = 0; i < 4; i++) {
            int c16 = a_c0 + i;
            cp16(sA + a_row * 128 + ((c16 ^ (a_row & 7)) << 4), Ag + kb + c16 * 16);
        }
        #pragma unroll
        for (int c16 = 0; c16 < 8; c16++) {
            cp16(sB + tid * 128 + ((c16 ^ (tid & 7)) << 4), Bg + kb + c16 * 16);
        }
    };

    int acc[4][8][4];
    #pragma unroll
    for (int mt = 0; mt < 4; mt++)
        #pragma unroll
        for (int nt = 0; nt < 8; nt++)
            #pragma unroll
            for (int r = 0; r < 4; r++) acc[mt][nt][r] = 0;

    // prologue
    #pragma unroll
    for (int p = 0; p < STAGES - 1; p++) {
        fill(p, p);
        asm volatile("cp.async.commit_group;" ::: "memory");
    }

    for (int j = 0; j < KITERS; j++) {
        asm volatile("cp.async.wait_group %0;" :: "n"(STAGES - 2) : "memory");
        __syncthreads();

        if (j + STAGES - 1 < KITERS)
            fill((j + STAGES - 1) & (STAGES - 1), j + STAGES - 1);
        asm volatile("cp.async.commit_group;" ::: "memory");

        const int st = j & (STAGES - 1);
        const uint32_t Ab = sb + st * STAGE_BYTES;
        const uint32_t Bb = Ab + A_BYTES;

        #pragma unroll
        for (int ks = 0; ks < 4; ks++) {
            // All fragment rows have (row & 7) == g, so the swizzled 16B chunk
            // for k-lo is (2ks)^g and k-hi is that ^1.
            const int cLo = (2 * ks) ^ g;
            const uint32_t offLo = ((uint32_t)cLo << 4) + tg * 4;
            const uint32_t offHi = ((uint32_t)(cLo ^ 1) << 4) + tg * 4;

            uint32_t af[4][4];
            #pragma unroll
            for (int mt = 0; mt < 4; mt++) {
                const uint32_t r0 = Ab + (wm + mt * 16 + g) * 128;
                af[mt][0] = lds32(r0 + offLo);            // row g,   k 0-15
                af[mt][1] = lds32(r0 + 8 * 128 + offLo);  // row g+8, k 0-15
                af[mt][2] = lds32(r0 + offHi);            // row g,   k 16-31
                af[mt][3] = lds32(r0 + 8 * 128 + offHi);  // row g+8, k 16-31
            }
            uint32_t bf[8][2];
            #pragma unroll
            for (int nt = 0; nt < 8; nt++) {
                const uint32_t r0 = Bb + (wn + nt * 8 + g) * 128;
                bf[nt][0] = lds32(r0 + offLo);  // n g, k 0-15
                bf[nt][1] = lds32(r0 + offHi);  // n g, k 16-31
            }
            #pragma unroll
            for (int mt = 0; mt < 4; mt++)
                #pragma unroll
                for (int nt = 0; nt < 8; nt++)
                    mma_s8(acc[mt][nt], af[mt], bf[nt][0], bf[nt][1]);
        }
    }

    // ---- epilogue: y = f32(acc) * (s_x * s_w[n]) + bias[n] ----
    const float* s_w = g_swapsb ? p_bias : p_sw;
    const float* bias = g_swapsb ? p_sw : p_bias;
    const float sx = __fdiv_rn(__uint_as_float(g_maxbits), 127.0f);
    #pragma unroll
    for (int nt = 0; nt < 8; nt++) {
        const int n = n0 + wn + nt * 8 + 2 * tg;
        const float s0 = __fmul_rn(sx, __ldg(s_w + n));
        const float s1 = __fmul_rn(sx, __ldg(s_w + n + 1));
        const float b0 = __ldg(bias + n);
        const float b1 = __ldg(bias + n + 1);
        #pragma unroll
        for (int mt = 0; mt < 4; mt++) {
            const int m = m0 + wm + mt * 16 + g;
            float2 v0, v1;
            v0.x = __fadd_rn(__fmul_rn(__int2float_rn(acc[mt][nt][0]), s0), b0);
            v0.y = __fadd_rn(__fmul_rn(__int2float_rn(acc[mt][nt][1]), s1), b1);
            v1.x = __fadd_rn(__fmul_rn(__int2float_rn(acc[mt][nt][2]), s0), b0);
            v1.y = __fadd_rn(__fmul_rn(__int2float_rn(acc[mt][nt][3]), s1), b1);
            *reinterpret_cast<float2*>(C + (size_t)m * NDIM + n) = v0;
            *reinterpret_cast<float2*>(C + (size_t)(m + 8) * NDIM + n) = v1;
        }
    }
}

// ======================= launch =======================
extern "C" void kernel_launch(void* const* d_in, const int* in_sizes, int n_in,
                              void* d_out, int out_size) {
    // Route by element count. w_q has N*K elements but is delivered as int32
    // words (harness dtypes are f32/i32/bf16 only) -> pack to int8 first.
    const float* x = nullptr;
    const int4* wq32 = nullptr;
    const float* small[2] = {nullptr, nullptr};
    int nsmall = 0;
    for (int i = 0; i < n_in; i++) {
        if (in_sizes[i] == MDIM * KDIM) x = (const float*)d_in[i];
        else if (in_sizes[i] == NDIM * KDIM) wq32 = (const int4*)d_in[i];
        else if (nsmall < 2) small[nsmall++] = (const float*)d_in[i];
    }
    const float* p_sw = small[0];
    const float* p_bias = small[1];
    float* out = (float*)d_out;

    k_init<<<1, 1>>>();
    k_detect<<<1, 32>>>(p_sw);
    k_maxabs<<<1184, 256>>>((const float4*)x, MDIM * KDIM / 4);
    k_quant<<<(MDIM * KDIM / 4) / 256, 256>>>((const float4*)x);
    k_wpack<<<(NDIM * KDIM / 4) / 256, 256>>>(wq32);

    cudaFuncSetAttribute(k_gemm, cudaFuncAttributeMaxDynamicSharedMemorySize,
                         SMEM_TOTAL);
    k_gemm<<<dim3(NDIM / BN, MDIM / BM), 256, SMEM_TOTAL>>>(p_sw, p_bias, out);
}

// round 6
// speedup vs baseline: 1.1792x; 1.1792x over previous
#include <cuda_runtime.h>
#include <cuda_bf16.h>
#include <cstdint>

// ======================= problem constants =======================
#define MDIM 8192
#define KDIM 4096
#define NDIM 4096
#define MHALF 4096

// ======================= int8 GEMM tiling =======================
constexpr int BM = 128;
constexpr int BN = 256;
constexpr int BK = 128;            // K bytes per stage (int8) -> 128B rows
constexpr int STAGES = 4;
constexpr int KITERS = KDIM / BK;  // 32
constexpr int A_BYTES = BM * BK;
constexpr int B_BYTES = BN * BK;
constexpr int STAGE_BYTES = A_BYTES + B_BYTES;
constexpr int SMEM_TOTAL = STAGES * STAGE_BYTES; // 192 KB

// ======================= bf16 GEMM tiling =======================
constexpr int HBM = 128;
constexpr int HBN = 128;
constexpr int HBK = 64;             // K elems per stage (bf16) -> 128B rows
constexpr int HSTAGES = 4;
constexpr int HKITERS = KDIM / HBK; // 64
constexpr int HA_BYTES = HBM * 128; // 16 KB
constexpr int HB_BYTES = HBN * 128; // 16 KB
constexpr int HSTAGE_BYTES = HA_BYTES + HB_BYTES;   // 32 KB
constexpr int HSMEM_TOTAL = HSTAGES * HSTAGE_BYTES; // 128 KB

// ======================= device scratch (no allocs allowed) =======================
__device__ __align__(1024) int8_t g_xq[(size_t)MDIM * KDIM];          // 32 MB
__device__ __align__(1024) int8_t g_wq[(size_t)NDIM * KDIM];          // 16 MB
__device__ __align__(1024) __nv_bfloat16 g_xb[(size_t)MHALF * KDIM];  // 32 MB (rows 4096..8191)
__device__ __align__(1024) __nv_bfloat16 g_wb[(size_t)NDIM * KDIM];   // 32 MB
__device__ unsigned int g_maxbits;
__device__ int g_swapsb;

// ======================= helpers =======================
__device__ __forceinline__ uint32_t smem_u32(const void* p) {
    uint32_t a;
    asm("{ .reg .u64 t; cvta.to.shared.u64 t, %1; cvt.u32.u64 %0, t; }"
        : "=r"(a) : "l"(p));
    return a;
}

__device__ __forceinline__ void cp16(uint32_t dst, const void* src) {
    asm volatile("cp.async.cg.shared.global [%0], [%1], 16;" :: "r"(dst), "l"(src));
}

__device__ __forceinline__ uint32_t lds32(uint32_t addr) {
    uint32_t v;
    asm volatile("ld.shared.b32 %0, [%1];" : "=r"(v) : "r"(addr));
    return v;
}

__device__ __forceinline__ void mma_s8(int* c, const uint32_t* a, uint32_t b0,
                                       uint32_t b1) {
    asm volatile(
        "mma.sync.aligned.m16n8k32.row.col.s32.s8.s8.s32 "
        "{%0,%1,%2,%3}, {%4,%5,%6,%7}, {%8,%9}, {%0,%1,%2,%3};"
        : "+r"(c[0]), "+r"(c[1]), "+r"(c[2]), "+r"(c[3])
        : "r"(a[0]), "r"(a[1]), "r"(a[2]), "r"(a[3]), "r"(b0), "r"(b1));
}

__device__ __forceinline__ void mma_bf16(float* c, const uint32_t* a,
                                         uint32_t b0, uint32_t b1) {
    asm volatile(
        "mma.sync.aligned.m16n8k16.row.col.f32.bf16.bf16.f32 "
        "{%0,%1,%2,%3}, {%4,%5,%6,%7}, {%8,%9}, {%0,%1,%2,%3};"
        : "+f"(c[0]), "+f"(c[1]), "+f"(c[2]), "+f"(c[3])
        : "r"(a[0]), "r"(a[1]), "r"(a[2]), "r"(a[3]), "r"(b0), "r"(b1));
}

// ======================= preprocessing =======================
__global__ void k_init() { g_maxbits = 0u; }

__global__ void k_maxabs(const float4* __restrict__ x, int n4) {
    unsigned int m = 0;
    for (int i = blockIdx.x * blockDim.x + threadIdx.x; i < n4;
         i += gridDim.x * blockDim.x) {
        float4 v = x[i];
        m = max(m, __float_as_uint(fabsf(v.x)));
        m = max(m, __float_as_uint(fabsf(v.y)));
        m = max(m, __float_as_uint(fabsf(v.z)));
        m = max(m, __float_as_uint(fabsf(v.w)));
    }
    #pragma unroll
    for (int o = 16; o > 0; o >>= 1)
        m = max(m, __shfl_xor_sync(0xffffffffu, m, o));
    if ((threadIdx.x & 31) == 0) atomicMax(&g_maxbits, m);
}

__global__ void k_detect(const float* __restrict__ cand_sw) {
    bool neg = false;
    for (int i = threadIdx.x; i < 256; i += 32) neg |= (cand_sw[i] < 0.0f);
    unsigned b = __ballot_sync(0xffffffffu, neg);
    if (threadIdx.x == 0) g_swapsb = (b != 0u);
}

// x -> int8 (all rows) and bf16 (upper-half rows), exact round-half-even.
__global__ void k_quant(const float4* __restrict__ x) {
    int i = blockIdx.x * blockDim.x + threadIdx.x;
    float sx = __fdiv_rn(__uint_as_float(g_maxbits), 127.0f);
    float4 v = x[i];
    float q0 = fminf(fmaxf(rintf(__fdiv_rn(v.x, sx)), -127.f), 127.f);
    float q1 = fminf(fmaxf(rintf(__fdiv_rn(v.y, sx)), -127.f), 127.f);
    float q2 = fminf(fmaxf(rintf(__fdiv_rn(v.z, sx)), -127.f), 127.f);
    float q3 = fminf(fmaxf(rintf(__fdiv_rn(v.w, sx)), -127.f), 127.f);
    int i0 = (int)q0, i1 = (int)q1, i2 = (int)q2, i3 = (int)q3;
    unsigned int u = (i0 & 0xFF) | ((i1 & 0xFF) << 8) | ((i2 & 0xFF) << 16) |
                     ((unsigned)(i3 & 0xFF) << 24);
    reinterpret_cast<unsigned int*>(g_xq)[i] = u;
    int row = i >> 10;  // KDIM/4 float4 per row
    if (row >= MHALF) {
        __nv_bfloat162 p0, p1;
        p0.x = __float2bfloat16(q0); p0.y = __float2bfloat16(q1);
        p1.x = __float2bfloat16(q2); p1.y = __float2bfloat16(q3);
        uint2 o;
        o.x = *reinterpret_cast<unsigned int*>(&p0);
        o.y = *reinterpret_cast<unsigned int*>(&p1);
        reinterpret_cast<uint2*>(g_xb)[i - MHALF * 1024] = o;
    }
}

// w_q int32 words -> packed int8 and bf16.
__global__ void k_wpack(const int4* __restrict__ w) {
    int i = blockIdx.x * blockDim.x + threadIdx.x;  // one int4 = 4 weights
    int4 p = w[i];
    unsigned int u = (p.x & 0xFF) | ((p.y & 0xFF) << 8) | ((p.z & 0xFF) << 16) |
                     ((unsigned)(p.w & 0xFF) << 24);
    reinterpret_cast<unsigned int*>(g_wq)[i] = u;
    __nv_bfloat162 h0, h1;
    h0.x = __float2bfloat16((float)p.x); h0.y = __float2bfloat16((float)p.y);
    h1.x = __float2bfloat16((float)p.z); h1.y = __float2bfloat16((float)p.w);
    uint2 o;
    o.x = *reinterpret_cast<unsigned int*>(&h0);
    o.y = *reinterpret_cast<unsigned int*>(&h1);
    reinterpret_cast<uint2*>(g_wb)[i] = o;
}

// ======================= int8 GEMM (rows 0..4095) =======================
__global__ void __launch_bounds__(256, 1)
k_gemm_i8(const float* __restrict__ p_sw, const float* __restrict__ p_bias,
          float* __restrict__ C) {
    extern __shared__ char smem[];
    const uint32_t sb = smem_u32(smem);
    const int tid = threadIdx.x;
    const int lane = tid & 31;
    const int wid = tid >> 5;
    const int g = lane >> 2;
    const int tg = lane & 3;
    const int wm = (wid >> 2) * 64;
    const int wn = (wid & 3) * 64;

    const int m0 = blockIdx.y * BM;
    const int n0 = blockIdx.x * BN;

    const int a_row = tid >> 1;
    const int a_c0 = (tid & 1) * 4;
    const int8_t* Ag = g_xq + (size_t)(m0 + a_row) * KDIM;
    const int8_t* Bg = g_wq + (size_t)(n0 + tid) * KDIM;

    auto fill = [&](int stage, int j) {
        const uint32_t sA = sb + stage * STAGE_BYTES;
        const uint32_t sB = sA + A_BYTES;
        const int kb = j * BK;
        #pragma unroll
        for (int i = 0; i < 4; i++) {
            int c16 = a_c0 + i;
            cp16(sA + a_row * 128 + ((c16 ^ (a_row & 7)) << 4), Ag + kb + c16 * 16);
        }
        #pragma unroll
        for (int c16 = 0; c16 < 8; c16++)
            cp16(sB + tid * 128 + ((c16 ^ (tid & 7)) << 4), Bg + kb + c16 * 16);
    };

    int acc[4][8][4];
    #pragma unroll
    for (int mt = 0; mt < 4; mt++)
        #pragma unroll
        for (int nt = 0; nt < 8; nt++)
            #pragma unroll
            for (int r = 0; r < 4; r++) acc[mt][nt][r] = 0;

    #pragma unroll
    for (int p = 0; p < STAGES - 1; p++) {
        fill(p, p);
        asm volatile("cp.async.commit_group;" ::: "memory");
    }

    for (int j = 0; j < KITERS; j++) {
        asm volatile("cp.async.wait_group %0;" :: "n"(STAGES - 2) : "memory");
        __syncthreads();
        if (j + STAGES - 1 < KITERS)
            fill((j + STAGES - 1) & (STAGES - 1), j + STAGES - 1);
        asm volatile("cp.async.commit_group;" ::: "memory");

        const int st = j & (STAGES - 1);
        const uint32_t Ab = sb + st * STAGE_BYTES;
        const uint32_t Bb = Ab + A_BYTES;

        #pragma unroll
        for (int ks = 0; ks < 4; ks++) {
            const int cLo = (2 * ks) ^ g;
            const uint32_t offLo = ((uint32_t)cLo << 4) + tg * 4;
            const uint32_t offHi = ((uint32_t)(cLo ^ 1) << 4) + tg * 4;
            uint32_t af[4][4];
            #pragma unroll
            for (int mt = 0; mt < 4; mt++) {
                const uint32_t r0 = Ab + (wm + mt * 16 + g) * 128;
                af[mt][0] = lds32(r0 + offLo);
                af[mt][1] = lds32(r0 + 8 * 128 + offLo);
                af[mt][2] = lds32(r0 + offHi);
                af[mt][3] = lds32(r0 + 8 * 128 + offHi);
            }
            uint32_t bf[8][2];
            #pragma unroll
            for (int nt = 0; nt < 8; nt++) {
                const uint32_t r0 = Bb + (wn + nt * 8 + g) * 128;
                bf[nt][0] = lds32(r0 + offLo);
                bf[nt][1] = lds32(r0 + offHi);
            }
            #pragma unroll
            for (int mt = 0; mt < 4; mt++)
                #pragma unroll
                for (int nt = 0; nt < 8; nt++)
                    mma_s8(acc[mt][nt], af[mt], bf[nt][0], bf[nt][1]);
        }
    }

    const float* s_w = g_swapsb ? p_bias : p_sw;
    const float* bias = g_swapsb ? p_sw : p_bias;
    const float sx = __fdiv_rn(__uint_as_float(g_maxbits), 127.0f);
    #pragma unroll
    for (int nt = 0; nt < 8; nt++) {
        const int n = n0 + wn + nt * 8 + 2 * tg;
        const float s0 = __fmul_rn(sx, __ldg(s_w + n));
        const float s1 = __fmul_rn(sx, __ldg(s_w + n + 1));
        const float b0 = __ldg(bias + n);
        const float b1 = __ldg(bias + n + 1);
        #pragma unroll
        for (int mt = 0; mt < 4; mt++) {
            const int m = m0 + wm + mt * 16 + g;
            float2 v0, v1;
            v0.x = __fadd_rn(__fmul_rn(__int2float_rn(acc[mt][nt][0]), s0), b0);
            v0.y = __fadd_rn(__fmul_rn(__int2float_rn(acc[mt][nt][1]), s1), b1);
            v1.x = __fadd_rn(__fmul_rn(__int2float_rn(acc[mt][nt][2]), s0), b0);
            v1.y = __fadd_rn(__fmul_rn(__int2float_rn(acc[mt][nt][3]), s1), b1);
            *reinterpret_cast<float2*>(C + (size_t)m * NDIM + n) = v0;
            *reinterpret_cast<float2*>(C + (size_t)(m + 8) * NDIM + n) = v1;
        }
    }
}

// ======================= bf16 GEMM (rows 4096..8191) =======================
__global__ void __launch_bounds__(256, 1)
k_gemm_bf(const float* __restrict__ p_sw, const float* __restrict__ p_bias,
          float* __restrict__ C) {
    extern __shared__ char smem[];
    const uint32_t sb = smem_u32(smem);
    const int tid = threadIdx.x;
    const int lane = tid & 31;
    const int wid = tid >> 5;
    const int g = lane >> 2;
    const int tg = lane & 3;
    const int wm = (wid >> 2) * 64;   // 2 warps along M (64 each)
    const int wn = (wid & 3) * 32;    // 4 warps along N (32 each)

    const int mloc = blockIdx.y * HBM;          // local row in g_xb
    const int n0 = blockIdx.x * HBN;

    const int a_row = tid >> 1;                 // 0..127
    const int a_c0 = (tid & 1) * 4;
    const __nv_bfloat16* Ag = g_xb + (size_t)(mloc + a_row) * KDIM;
    const __nv_bfloat16* Bg = g_wb + (size_t)(n0 + a_row) * KDIM;

    auto fill = [&](int stage, int j) {
        const uint32_t sA = sb + stage * HSTAGE_BYTES;
        const uint32_t sB = sA + HA_BYTES;
        const int kb = j * 128;  // bytes: HBK elems * 2
        #pragma unroll
        for (int i = 0; i < 4; i++) {
            int c16 = a_c0 + i;
            uint32_t soff = a_row * 128 + ((c16 ^ (a_row & 7)) << 4);
            cp16(sA + soff, (const char*)Ag + kb + c16 * 16);
            cp16(sB + soff, (const char*)Bg + kb + c16 * 16);
        }
    };

    float acc[4][4][4];
    #pragma unroll
    for (int mt = 0; mt < 4; mt++)
        #pragma unroll
        for (int nt = 0; nt < 4; nt++)
            #pragma unroll
            for (int r = 0; r < 4; r++) acc[mt][nt][r] = 0.0f;

    #pragma unroll
    for (int p = 0; p < HSTAGES - 1; p++) {
        fill(p, p);
        asm volatile("cp.async.commit_group;" ::: "memory");
    }

    for (int j = 0; j < HKITERS; j++) {
        asm volatile("cp.async.wait_group %0;" :: "n"(HSTAGES - 2) : "memory");
        __syncthreads();
        if (j + HSTAGES - 1 < HKITERS)
            fill((j + HSTAGES - 1) & (HSTAGES - 1), j + HSTAGES - 1);
        asm volatile("cp.async.commit_group;" ::: "memory");

        const int st = j & (HSTAGES - 1);
        const uint32_t Ab = sb + st * HSTAGE_BYTES;
        const uint32_t Bb = Ab + HA_BYTES;

        // 4 k-steps of 16 bf16 elems (= 32B = two 16B chunks) each
        #pragma unroll
        for (int ks = 0; ks < 4; ks++) {
            const int cLo = (2 * ks) ^ g;
            const uint32_t offLo = ((uint32_t)cLo << 4) + tg * 4;
            const uint32_t offHi = ((uint32_t)(cLo ^ 1) << 4) + tg * 4;
            uint32_t af[4][4];
            #pragma unroll
            for (int mt = 0; mt < 4; mt++) {
                const uint32_t r0 = Ab + (wm + mt * 16 + g) * 128;
                af[mt][0] = lds32(r0 + offLo);            // row g,   k 0-7
                af[mt][1] = lds32(r0 + 8 * 128 + offLo);  // row g+8, k 0-7
                af[mt][2] = lds32(r0 + offHi);            // row g,   k 8-15
                af[mt][3] = lds32(r0 + 8 * 128 + offHi);  // row g+8, k 8-15
            }
            uint32_t bfr[4][2];
            #pragma unroll
            for (int nt = 0; nt < 4; nt++) {
                const uint32_t r0 = Bb + (wn + nt * 8 + g) * 128;
                bfr[nt][0] = lds32(r0 + offLo);
                bfr[nt][1] = lds32(r0 + offHi);
            }
            #pragma unroll
            for (int mt = 0; mt < 4; mt++)
                #pragma unroll
                for (int nt = 0; nt < 4; nt++)
                    mma_bf16(acc[mt][nt], af[mt], bfr[nt][0], bfr[nt][1]);
        }
    }

    const float* s_w = g_swapsb ? p_bias : p_sw;
    const float* bias = g_swapsb ? p_sw : p_bias;
    const float sx = __fdiv_rn(__uint_as_float(g_maxbits), 127.0f);
    #pragma unroll
    for (int nt = 0; nt < 4; nt++) {
        const int n = n0 + wn + nt * 8 + 2 * tg;
        const float s0 = __fmul_rn(sx, __ldg(s_w + n));
        const float s1 = __fmul_rn(sx, __ldg(s_w + n + 1));
        const float b0 = __ldg(bias + n);
        const float b1 = __ldg(bias + n + 1);
        #pragma unroll
        for (int mt = 0; mt < 4; mt++) {
            const int m = MHALF + mloc + wm + mt * 16 + g;
            float2 v0, v1;
            v0.x = __fadd_rn(__fmul_rn(acc[mt][nt][0], s0), b0);
            v0.y = __fadd_rn(__fmul_rn(acc[mt][nt][1], s1), b1);
            v1.x = __fadd_rn(__fmul_rn(acc[mt][nt][2], s0), b0);
            v1.y = __fadd_rn(__fmul_rn(acc[mt][nt][3], s1), b1);
            *reinterpret_cast<float2*>(C + (size_t)m * NDIM + n) = v0;
            *reinterpret_cast<float2*>(C + (size_t)(m + 8) * NDIM + n) = v1;
        }
    }
}

// ======================= launch =======================
extern "C" void kernel_launch(void* const* d_in, const int* in_sizes, int n_in,
                              void* d_out, int out_size) {
    const float* x = nullptr;
    const int4* wq32 = nullptr;
    const float* small[2] = {nullptr, nullptr};
    int nsmall = 0;
    for (int i = 0; i < n_in; i++) {
        if (in_sizes[i] == MDIM * KDIM) x = (const float*)d_in[i];
        else if (in_sizes[i] == NDIM * KDIM) wq32 = (const int4*)d_in[i];
        else if (nsmall < 2) small[nsmall++] = (const float*)d_in[i];
    }
    const float* p_sw = small[0];
    const float* p_bias = small[1];
    float* out = (float*)d_out;

    k_init<<<1, 1>>>();
    k_detect<<<1, 32>>>(p_sw);
    k_maxabs<<<1184, 256>>>((const float4*)x, MDIM * KDIM / 4);
    k_quant<<<(MDIM * KDIM / 4) / 256, 256>>>((const float4*)x);
    k_wpack<<<(NDIM * KDIM / 4) / 256, 256>>>(wq32);

    cudaFuncSetAttribute(k_gemm_i8, cudaFuncAttributeMaxDynamicSharedMemorySize,
                         SMEM_TOTAL);
    cudaFuncSetAttribute(k_gemm_bf, cudaFuncAttributeMaxDynamicSharedMemorySize,
                         HSMEM_TOTAL);
    // rows 0..4095 via int8/dp4a path
    k_gemm_i8<<<dim3(NDIM / BN, MHALF / BM), 256, SMEM_TOTAL>>>(p_sw, p_bias, out);
    // rows 4096..8191 via bf16 HMMA path
    k_gemm_bf<<<dim3(NDIM / HBN, MHALF / HBM), 256, HSMEM_TOTAL>>>(p_sw, p_bias, out);
}

// round 8
// speedup vs baseline: 1.8774x; 1.5921x over previous
#include <cuda_runtime.h>
#include <cuda_bf16.h>
#include <cstdint>

// ======================= problem constants =======================
#define MDIM 8192
#define KDIM 4096
#define NDIM 4096

// ======================= bf16 GEMM tiling =======================
constexpr int BM = 128;             // CTA M tile
constexpr int BN = 256;             // CTA N tile
constexpr int BK = 64;              // K elems per stage (bf16) -> 128B rows
constexpr int STAGES = 4;
constexpr int KITERS = KDIM / BK;   // 64
constexpr int A_BYTES = BM * 128;   // 16 KB
constexpr int B_BYTES = BN * 128;   // 32 KB
constexpr int STAGE_BYTES = A_BYTES + B_BYTES;   // 48 KB
constexpr int SMEM_TOTAL = STAGES * STAGE_BYTES; // 192 KB

// ======================= device scratch (no allocs allowed) =======================
__device__ __align__(1024) __nv_bfloat16 g_xb[(size_t)MDIM * KDIM]; // 64 MB
__device__ __align__(1024) __nv_bfloat16 g_wb[(size_t)NDIM * KDIM]; // 32 MB
__device__ unsigned int g_maxbits;
__device__ int g_swapsb;

// ======================= helpers =======================
__device__ __forceinline__ uint32_t smem_u32(const void* p) {
    uint32_t a;
    asm("{ .reg .u64 t; cvta.to.shared.u64 t, %1; cvt.u32.u64 %0, t; }"
        : "=r"(a) : "l"(p));
    return a;
}

__device__ __forceinline__ void cp16(uint32_t dst, const void* src) {
    asm volatile("cp.async.cg.shared.global [%0], [%1], 16;" :: "r"(dst), "l"(src));
}

__device__ __forceinline__ void ldsm4(uint32_t& r0, uint32_t& r1, uint32_t& r2,
                                      uint32_t& r3, uint32_t addr) {
    asm volatile("ldmatrix.sync.aligned.m8n8.x4.shared.b16 {%0,%1,%2,%3}, [%4];"
                 : "=r"(r0), "=r"(r1), "=r"(r2), "=r"(r3) : "r"(addr));
}

__device__ __forceinline__ void mma_bf16(float* c, const uint32_t* a,
                                         uint32_t b0, uint32_t b1) {
    asm volatile(
        "mma.sync.aligned.m16n8k16.row.col.f32.bf16.bf16.f32 "
        "{%0,%1,%2,%3}, {%4,%5,%6,%7}, {%8,%9}, {%0,%1,%2,%3};"
        : "+f"(c[0]), "+f"(c[1]), "+f"(c[2]), "+f"(c[3])
        : "r"(a[0]), "r"(a[1]), "r"(a[2]), "r"(a[3]), "r"(b0), "r"(b1));
}

// ======================= preprocessing =======================
__global__ void k_init() { g_maxbits = 0u; }

__global__ void k_maxabs(const float4* __restrict__ x, int n4) {
    unsigned int m = 0;
    for (int i = blockIdx.x * blockDim.x + threadIdx.x; i < n4;
         i += gridDim.x * blockDim.x) {
        float4 v = x[i];
        m = max(m, __float_as_uint(fabsf(v.x)));
        m = max(m, __float_as_uint(fabsf(v.y)));
        m = max(m, __float_as_uint(fabsf(v.z)));
        m = max(m, __float_as_uint(fabsf(v.w)));
    }
    #pragma unroll
    for (int o = 16; o > 0; o >>= 1)
        m = max(m, __shfl_xor_sync(0xffffffffu, m, o));
    if ((threadIdx.x & 31) == 0) atomicMax(&g_maxbits, m);
}

// s_w is strictly positive by construction; bias has negatives.
__global__ void k_detect(const float* __restrict__ cand_sw) {
    bool neg = false;
    for (int i = threadIdx.x; i < 256; i += 32) neg |= (cand_sw[i] < 0.0f);
    unsigned b = __ballot_sync(0xffffffffu, neg);
    if (threadIdx.x == 0) g_swapsb = (b != 0u);
}

// x -> int8-valued bf16, exact: round-half-even(x / s_x) clamped to [-127,127].
__global__ void k_quant(const float4* __restrict__ x) {
    int i = blockIdx.x * blockDim.x + threadIdx.x;
    float sx = __fdiv_rn(__uint_as_float(g_maxbits), 127.0f);
    float4 v = x[i];
    float q0 = fminf(fmaxf(rintf(__fdiv_rn(v.x, sx)), -127.f), 127.f);
    float q1 = fminf(fmaxf(rintf(__fdiv_rn(v.y, sx)), -127.f), 127.f);
    float q2 = fminf(fmaxf(rintf(__fdiv_rn(v.z, sx)), -127.f), 127.f);
    float q3 = fminf(fmaxf(rintf(__fdiv_rn(v.w, sx)), -127.f), 127.f);
    __nv_bfloat162 p0, p1;
    p0.x = __float2bfloat16(q0); p0.y = __float2bfloat16(q1);
    p1.x = __float2bfloat16(q2); p1.y = __float2bfloat16(q3);
    uint2 o;
    o.x = *reinterpret_cast<unsigned int*>(&p0);
    o.y = *reinterpret_cast<unsigned int*>(&p1);
    reinterpret_cast<uint2*>(g_xb)[i] = o;
}

// w_q int32 words -> bf16 (values in [-127,127], exact in bf16).
__global__ void k_wpack(const int4* __restrict__ w) {
    int i = blockIdx.x * blockDim.x + threadIdx.x;  // one int4 = 4 weights
    int4 p = w[i];
    __nv_bfloat162 h0, h1;
    h0.x = __float2bfloat16((float)p.x); h0.y = __float2bfloat16((float)p.y);
    h1.x = __float2bfloat16((float)p.z); h1.y = __float2bfloat16((float)p.w);
    uint2 o;
    o.x = *reinterpret_cast<unsigned int*>(&h0);
    o.y = *reinterpret_cast<unsigned int*>(&h1);
    reinterpret_cast<uint2*>(g_wb)[i] = o;
}

// ======================= bf16 HMMA GEMM =======================
__global__ void __launch_bounds__(256, 1)
k_gemm(const float* __restrict__ p_sw, const float* __restrict__ p_bias,
       float* __restrict__ C) {
    extern __shared__ char smem[];
    const uint32_t sb = smem_u32(smem);
    const int tid = threadIdx.x;
    const int lane = tid & 31;
    const int wid = tid >> 5;
    const int g = lane >> 2;        // fragment row group 0..7
    const int tg = lane & 3;        // thread-in-group 0..3
    const int q = lane >> 3;        // ldmatrix quad 0..3
    const int l = lane & 7;         // lane-in-quad
    const int wm = (wid >> 2) * 64; // 2 warps along M (64 rows each)
    const int wn = (wid & 3) * 64;  // 4 warps along N (64 cols each)

    const int m0 = blockIdx.y * BM;
    const int n0 = blockIdx.x * BN;

    // ---- async fill (16B chunks, XOR-swizzled within 128B rows) ----
    const int a_row = tid >> 1;           // 0..127
    const int a_c0 = (tid & 1) * 4;       // 0 or 4
    const __nv_bfloat16* Ag = g_xb + (size_t)(m0 + a_row) * KDIM;
    const __nv_bfloat16* Bg = g_wb + (size_t)(n0 + tid) * KDIM;

    auto fill = [&](int stage, int j) {
        const uint32_t sA = sb + stage * STAGE_BYTES;
        const uint32_t sB = sA + A_BYTES;
        const int kb = j * 128;  // bytes: BK elems * 2
        #pragma unroll
        for (int i = 0; i < 4; i++) {
            int c16 = a_c0 + i;
            cp16(sA + a_row * 128 + ((c16 ^ (a_row & 7)) << 4),
                 (const char*)Ag + kb + c16 * 16);
        }
        #pragma unroll
        for (int c16 = 0; c16 < 8; c16++)
            cp16(sB + tid * 128 + ((c16 ^ (tid & 7)) << 4),
                 (const char*)Bg + kb + c16 * 16);
    };

    float acc[4][8][4];
    #pragma unroll
    for (int mt = 0; mt < 4; mt++)
        #pragma unroll
        for (int nt = 0; nt < 8; nt++)
            #pragma unroll
            for (int r = 0; r < 4; r++) acc[mt][nt][r] = 0.0f;

    #pragma unroll
    for (int p = 0; p < STAGES - 1; p++) {
        fill(p, p);
        asm volatile("cp.async.commit_group;" ::: "memory");
    }

    for (int j = 0; j < KITERS; j++) {
        asm volatile("cp.async.wait_group %0;" :: "n"(STAGES - 2) : "memory");
        __syncthreads();
        if (j + STAGES - 1 < KITERS)
            fill((j + STAGES - 1) & (STAGES - 1), j + STAGES - 1);
        asm volatile("cp.async.commit_group;" ::: "memory");

        const int st = j & (STAGES - 1);
        const uint32_t Ab = sb + st * STAGE_BYTES;
        const uint32_t Bb = Ab + A_BYTES;

        // 4 k-steps of 16 bf16 elems (= two 16B chunks) each
        #pragma unroll
        for (int ks = 0; ks < 4; ks++) {
            // A: ldmatrix.x4 -> a0(row g,k-lo) a1(row g+8,k-lo) a2(g,k-hi) a3(g+8,k-hi)
            // quads 0,1 -> rows 0-7 / 8-15 at k-lo; quads 2,3 -> same rows at k-hi
            uint32_t af[4][4];
            #pragma unroll
            for (int mt = 0; mt < 4; mt++) {
                int row = wm + mt * 16 + (q & 1) * 8 + l;
                int c = (2 * ks + (q >> 1)) ^ (row & 7);
                ldsm4(af[mt][0], af[mt][1], af[mt][2], af[mt][3],
                      Ab + row * 128 + (c << 4));
            }
            // B: ldmatrix.x4 -> b0(n-tile even,k-lo) b1(even,k-hi) b2(odd,k-lo) b3(odd,k-hi)
            // quads 0,1 -> n rows 0-7 at k-lo/k-hi; quads 2,3 -> n rows 8-15
            uint32_t bfr[4][4];
            #pragma unroll
            for (int nb = 0; nb < 4; nb++) {
                int nrow = wn + nb * 16 + (q >> 1) * 8 + l;
                int c = (2 * ks + (q & 1)) ^ (nrow & 7);
                ldsm4(bfr[nb][0], bfr[nb][1], bfr[nb][2], bfr[nb][3],
                      Bb + nrow * 128 + (c << 4));
            }
            #pragma unroll
            for (int mt = 0; mt < 4; mt++)
                #pragma unroll
                for (int nb = 0; nb < 4; nb++) {
                    mma_bf16(acc[mt][2 * nb], af[mt], bfr[nb][0], bfr[nb][1]);
                    mma_bf16(acc[mt][2 * nb + 1], af[mt], bfr[nb][2], bfr[nb][3]);
                }
        }
    }

    // ---- epilogue: y = acc * (s_x * s_w[n]) + bias[n] ----
    const float* s_w = g_swapsb ? p_bias : p_sw;
    const float* bias = g_swapsb ? p_sw : p_bias;
    const float sx = __fdiv_rn(__uint_as_float(g_maxbits), 127.0f);
    #pragma unroll
    for (int nt = 0; nt < 8; nt++) {
        const int n = n0 + wn + nt * 8 + 2 * tg;
        const float s0 = __fmul_rn(sx, __ldg(s_w + n));
        const float s1 = __fmul_rn(sx, __ldg(s_w + n + 1));
        const float b0 = __ldg(bias + n);
        const float b1 = __ldg(bias + n + 1);
        #pragma unroll
        for (int mt = 0; mt < 4; mt++) {
            const int m = m0 + wm + mt * 16 + g;
            float2 v0, v1;
            v0.x = __fadd_rn(__fmul_rn(acc[mt][nt][0], s0), b0);
            v0.y = __fadd_rn(__fmul_rn(acc[mt][nt][1], s1), b1);
            v1.x = __fadd_rn(__fmul_rn(acc[mt][nt][2], s0), b0);
            v1.y = __fadd_rn(__fmul_rn(acc[mt][nt][3], s1), b1);
            *reinterpret_cast<float2*>(C + (size_t)m * NDIM + n) = v0;
            *reinterpret_cast<float2*>(C + (size_t)(m + 8) * NDIM + n) = v1;
        }
    }
}

// ======================= launch =======================
extern "C" void kernel_launch(void* const* d_in, const int* in_sizes, int n_in,
                              void* d_out, int out_size) {
    const float* x = nullptr;
    const int4* wq32 = nullptr;
    const float* small[2] = {nullptr, nullptr};
    int nsmall = 0;
    for (int i = 0; i < n_in; i++) {
        if (in_sizes[i] == MDIM * KDIM) x = (const float*)d_in[i];
        else if (in_sizes[i] == NDIM * KDIM) wq32 = (const int4*)d_in[i];
        else if (nsmall < 2) small[nsmall++] = (const float*)d_in[i];
    }
    const float* p_sw = small[0];
    const float* p_bias = small[1];
    float* out = (float*)d_out;

    k_init<<<1, 1>>>();
    k_detect<<<1, 32>>>(p_sw);
    k_maxabs<<<1184, 256>>>((const float4*)x, MDIM * KDIM / 4);
    k_quant<<<(MDIM * KDIM / 4) / 256, 256>>>((const float4*)x);
    k_wpack<<<(NDIM * KDIM / 4) / 256, 256>>>(wq32);

    cudaFuncSetAttribute(k_gemm, cudaFuncAttributeMaxDynamicSharedMemorySize,
                         SMEM_TOTAL);
    k_gemm<<<dim3(NDIM / BN, MDIM / BM), 256, SMEM_TOTAL>>>(p_sw, p_bias, out);
}

// round 9
// speedup vs baseline: 1.9247x; 1.0252x over previous
#include <cuda_runtime.h>
#include <cuda_bf16.h>
#include <cstdint>

// ======================= problem constants =======================
#define MDIM 8192
#define KDIM 4096
#define NDIM 4096

// ======================= bf16 GEMM tiling =======================
constexpr int BM = 128;             // CTA M tile
constexpr int BN = 256;             // CTA N tile
constexpr int BK = 64;              // K elems per stage (bf16) -> 128B rows
constexpr int STAGES = 4;
constexpr int KITERS = KDIM / BK;   // 64
constexpr int A_BYTES = BM * 128;   // 16 KB
constexpr int B_BYTES = BN * 128;   // 32 KB
constexpr int STAGE_BYTES = A_BYTES + B_BYTES;   // 48 KB
constexpr int SMEM_TOTAL = STAGES * STAGE_BYTES; // 192 KB

// ======================= device scratch (no allocs allowed) =======================
__device__ __align__(1024) __nv_bfloat16 g_xb[(size_t)MDIM * KDIM]; // 64 MB
__device__ __align__(1024) __nv_bfloat16 g_wb[(size_t)NDIM * KDIM]; // 32 MB
__device__ unsigned int g_maxbits;
__device__ int g_swapsb;

// ======================= helpers =======================
__device__ __forceinline__ uint32_t smem_u32(const void* p) {
    uint32_t a;
    asm("{ .reg .u64 t; cvta.to.shared.u64 t, %1; cvt.u32.u64 %0, t; }"
        : "=r"(a) : "l"(p));
    return a;
}

__device__ __forceinline__ void cp16(uint32_t dst, const void* src) {
    asm volatile("cp.async.cg.shared.global [%0], [%1], 16;" :: "r"(dst), "l"(src));
}

__device__ __forceinline__ void ldsm4(uint32_t& r0, uint32_t& r1, uint32_t& r2,
                                      uint32_t& r3, uint32_t addr) {
    asm volatile("ldmatrix.sync.aligned.m8n8.x4.shared.b16 {%0,%1,%2,%3}, [%4];"
                 : "=r"(r0), "=r"(r1), "=r"(r2), "=r"(r3) : "r"(addr));
}

__device__ __forceinline__ void mma_bf16(float* c, const uint32_t* a,
                                         uint32_t b0, uint32_t b1) {
    asm volatile(
        "mma.sync.aligned.m16n8k16.row.col.f32.bf16.bf16.f32 "
        "{%0,%1,%2,%3}, {%4,%5,%6,%7}, {%8,%9}, {%0,%1,%2,%3};"
        : "+f"(c[0]), "+f"(c[1]), "+f"(c[2]), "+f"(c[3])
        : "r"(a[0]), "r"(a[1]), "r"(a[2]), "r"(a[3]), "r"(b0), "r"(b1));
}

// ======================= preprocessing =======================
// init + s_w/bias disambiguation in one launch (s_w strictly positive).
__global__ void k_detect(const float* __restrict__ cand_sw) {
    if (threadIdx.x == 0) g_maxbits = 0u;
    bool neg = false;
    for (int i = threadIdx.x; i < 256; i += 32) neg |= (cand_sw[i] < 0.0f);
    unsigned b = __ballot_sync(0xffffffffu, neg);
    if (threadIdx.x == 0) g_swapsb = (b != 0u);
}

__global__ void k_maxabs(const float4* __restrict__ x, int n4) {
    unsigned int m = 0;
    for (int i = blockIdx.x * blockDim.x + threadIdx.x; i < n4;
         i += gridDim.x * blockDim.x) {
        float4 v = x[i];
        m = max(m, __float_as_uint(fabsf(v.x)));
        m = max(m, __float_as_uint(fabsf(v.y)));
        m = max(m, __float_as_uint(fabsf(v.z)));
        m = max(m, __float_as_uint(fabsf(v.w)));
    }
    #pragma unroll
    for (int o = 16; o > 0; o >>= 1)
        m = max(m, __shfl_xor_sync(0xffffffffu, m, o));
    if ((threadIdx.x & 31) == 0) atomicMax(&g_maxbits, m);
}

// x -> int8-valued bf16, exact: round-half-even(x / s_x) clamped to [-127,127].
__global__ void k_quant(const float4* __restrict__ x) {
    int i = blockIdx.x * blockDim.x + threadIdx.x;
    float sx = __fdiv_rn(__uint_as_float(g_maxbits), 127.0f);
    float4 v = x[i];
    float q0 = fminf(fmaxf(rintf(__fdiv_rn(v.x, sx)), -127.f), 127.f);
    float q1 = fminf(fmaxf(rintf(__fdiv_rn(v.y, sx)), -127.f), 127.f);
    float q2 = fminf(fmaxf(rintf(__fdiv_rn(v.z, sx)), -127.f), 127.f);
    float q3 = fminf(fmaxf(rintf(__fdiv_rn(v.w, sx)), -127.f), 127.f);
    __nv_bfloat162 p0, p1;
    p0.x = __float2bfloat16(q0); p0.y = __float2bfloat16(q1);
    p1.x = __float2bfloat16(q2); p1.y = __float2bfloat16(q3);
    uint2 o;
    o.x = *reinterpret_cast<unsigned int*>(&p0);
    o.y = *reinterpret_cast<unsigned int*>(&p1);
    reinterpret_cast<uint2*>(g_xb)[i] = o;
}

// w_q int32 words -> bf16 (values in [-127,127], exact in bf16).
__global__ void k_wpack(const int4* __restrict__ w) {
    int i = blockIdx.x * blockDim.x + threadIdx.x;  // one int4 = 4 weights
    int4 p = w[i];
    __nv_bfloat162 h0, h1;
    h0.x = __float2bfloat16((float)p.x); h0.y = __float2bfloat16((float)p.y);
    h1.x = __float2bfloat16((float)p.z); h1.y = __float2bfloat16((float)p.w);
    uint2 o;
    o.x = *reinterpret_cast<unsigned int*>(&h0);
    o.y = *reinterpret_cast<unsigned int*>(&h1);
    reinterpret_cast<uint2*>(g_wb)[i] = o;
}

// ======================= bf16 HMMA GEMM (fragment-pipelined) =======================
__global__ void __launch_bounds__(256, 1)
k_gemm(const float* __restrict__ p_sw, const float* __restrict__ p_bias,
       float* __restrict__ C) {
    extern __shared__ char smem[];
    const uint32_t sb = smem_u32(smem);
    const int tid = threadIdx.x;
    const int lane = tid & 31;
    const int wid = tid >> 5;
    const int g = lane >> 2;        // fragment row group 0..7
    const int tg = lane & 3;        // thread-in-group 0..3
    const int q = lane >> 3;        // ldmatrix quad 0..3
    const int l = lane & 7;         // lane-in-quad
    const int wm = (wid >> 2) * 64; // 2 warps along M (64 rows each)
    const int wn = (wid & 3) * 64;  // 4 warps along N (64 cols each)

    const int m0 = blockIdx.y * BM;
    const int n0 = blockIdx.x * BN;

    // ---- async fill (16B chunks, XOR-swizzled within 128B rows) ----
    const int a_row = tid >> 1;           // 0..127
    const int a_c0 = (tid & 1) * 4;       // 0 or 4
    const __nv_bfloat16* Ag = g_xb + (size_t)(m0 + a_row) * KDIM;
    const __nv_bfloat16* Bg = g_wb + (size_t)(n0 + tid) * KDIM;

    auto fill = [&](int stage, int j) {
        const uint32_t sA = sb + stage * STAGE_BYTES;
        const uint32_t sB = sA + A_BYTES;
        const int kb = j * 128;  // bytes: BK elems * 2
        #pragma unroll
        for (int i = 0; i < 4; i++) {
            int c16 = a_c0 + i;
            cp16(sA + a_row * 128 + ((c16 ^ (a_row & 7)) << 4),
                 (const char*)Ag + kb + c16 * 16);
        }
        #pragma unroll
        for (int c16 = 0; c16 < 8; c16++)
            cp16(sB + tid * 128 + ((c16 ^ (tid & 7)) << 4),
                 (const char*)Bg + kb + c16 * 16);
    };

    // per-warp fragment base rows (ks-independent parts)
    const int arow_base = (q & 1) * 8 + l;   // + wm + mt*16
    const int ac_sel = q >> 1;               // k-half select for A
    const int brow_base = (q >> 1) * 8 + l;  // + wn + nb*16
    const int bc_sel = q & 1;                // k-half select for B

    // load all 8 fragments (4 A + 4 B) for one k-step from a given stage base
    auto load_frags = [&](uint32_t Ab, uint32_t Bb, int ks,
                          uint32_t af[4][4], uint32_t bfr[4][4]) {
        #pragma unroll
        for (int mt = 0; mt < 4; mt++) {
            int row = wm + mt * 16 + arow_base;
            int c = (2 * ks + ac_sel) ^ (row & 7);
            ldsm4(af[mt][0], af[mt][1], af[mt][2], af[mt][3],
                  Ab + row * 128 + (c << 4));
        }
        #pragma unroll
        for (int nb = 0; nb < 4; nb++) {
            int nrow = wn + nb * 16 + brow_base;
            int c = (2 * ks + bc_sel) ^ (nrow & 7);
            ldsm4(bfr[nb][0], bfr[nb][1], bfr[nb][2], bfr[nb][3],
                  Bb + nrow * 128 + (c << 4));
        }
    };

    float acc[4][8][4];
    #pragma unroll
    for (int mt = 0; mt < 4; mt++)
        #pragma unroll
        for (int nt = 0; nt < 8; nt++)
            #pragma unroll
            for (int r = 0; r < 4; r++) acc[mt][nt][r] = 0.0f;

    #pragma unroll
    for (int p = 0; p < STAGES - 1; p++) {
        fill(p, p);
        asm volatile("cp.async.commit_group;" ::: "memory");
    }

    uint32_t af[2][4][4], bfr[2][4][4];

    for (int j = 0; j < KITERS; j++) {
        // wait_group(1): stages j AND j+1 resident -> cross-iter frag prefetch is safe
        asm volatile("cp.async.wait_group %0;" :: "n"(1) : "memory");
        __syncthreads();
        if (j + STAGES - 1 < KITERS)
            fill((j + STAGES - 1) & (STAGES - 1), j + STAGES - 1);
        asm volatile("cp.async.commit_group;" ::: "memory");

        const uint32_t Ab = sb + (j & (STAGES - 1)) * STAGE_BYTES;
        const uint32_t Bb = Ab + A_BYTES;

        if (j == 0) load_frags(Ab, Bb, 0, af[0], bfr[0]);  // one-time bubble

        #pragma unroll
        for (int ks = 0; ks < 4; ks++) {
            const int cur = ks & 1, nxt = cur ^ 1;
            if (ks < 3) {
                load_frags(Ab, Bb, ks + 1, af[nxt], bfr[nxt]);
            } else if (j + 1 < KITERS) {
                // prefetch ks=0 of next stage (resident per wait_group(1))
                const uint32_t Ab2 = sb + ((j + 1) & (STAGES - 1)) * STAGE_BYTES;
                load_frags(Ab2, Ab2 + A_BYTES, 0, af[nxt], bfr[nxt]);
            }
            #pragma unroll
            for (int mt = 0; mt < 4; mt++)
                #pragma unroll
                for (int nb = 0; nb < 4; nb++) {
                    mma_bf16(acc[mt][2 * nb], af[cur][mt], bfr[cur][nb][0],
                             bfr[cur][nb][1]);
                    mma_bf16(acc[mt][2 * nb + 1], af[cur][mt], bfr[cur][nb][2],
                             bfr[cur][nb][3]);
                }
        }
    }

    // ---- epilogue: y = acc * (s_x * s_w[n]) + bias[n] ----
    const float* s_w = g_swapsb ? p_bias : p_sw;
    const float* bias = g_swapsb ? p_sw : p_bias;
    const float sx = __fdiv_rn(__uint_as_float(g_maxbits), 127.0f);
    #pragma unroll
    for (int nt = 0; nt < 8; nt++) {
        const int n = n0 + wn + nt * 8 + 2 * tg;
        const float s0 = __fmul_rn(sx, __ldg(s_w + n));
        const float s1 = __fmul_rn(sx, __ldg(s_w + n + 1));
        const float b0 = __ldg(bias + n);
        const float b1 = __ldg(bias + n + 1);
        #pragma unroll
        for (int mt = 0; mt < 4; mt++) {
            const int m = m0 + wm + mt * 16 + g;
            float2 v0, v1;
            v0.x = __fadd_rn(__fmul_rn(acc[mt][nt][0], s0), b0);
            v0.y = __fadd_rn(__fmul_rn(acc[mt][nt][1], s1), b1);
            v1.x = __fadd_rn(__fmul_rn(acc[mt][nt][2], s0), b0);
            v1.y = __fadd_rn(__fmul_rn(acc[mt][nt][3], s1), b1);
            *reinterpret_cast<float2*>(C + (size_t)m * NDIM + n) = v0;
            *reinterpret_cast<float2*>(C + (size_t)(m + 8) * NDIM + n) = v1;
        }
    }
}

// ======================= launch =======================
extern "C" void kernel_launch(void* const* d_in, const int* in_sizes, int n_in,
                              void* d_out, int out_size) {
    const float* x = nullptr;
    const int4* wq32 = nullptr;
    const float* small[2] = {nullptr, nullptr};
    int nsmall = 0;
    for (int i = 0; i < n_in; i++) {
        if (in_sizes[i] == MDIM * KDIM) x = (const float*)d_in[i];
        else if (in_sizes[i] == NDIM * KDIM) wq32 = (const int4*)d_in[i];
        else if (nsmall < 2) small[nsmall++] = (const float*)d_in[i];
    }
    const float* p_sw = small[0];
    const float* p_bias = small[1];
    float* out = (float*)d_out;

    k_detect<<<1, 32>>>(p_sw);
    k_maxabs<<<1184, 256>>>((const float4*)x, MDIM * KDIM / 4);
    k_quant<<<(MDIM * KDIM / 4) / 256, 256>>>((const float4*)x);
    k_wpack<<<(NDIM * KDIM / 4) / 256, 256>>>(wq32);

    cudaFuncSetAttribute(k_gemm, cudaFuncAttributeMaxDynamicSharedMemorySize,
                         SMEM_TOTAL);
    k_gemm<<<dim3(NDIM / BN, MDIM / BM), 256, SMEM_TOTAL>>>(p_sw, p_bias, out);
}